// round 9
// baseline (speedup 1.0000x reference)
#include <cuda_runtime.h>
#include <stdint.h>

// cdist: out[i,j] = sqrt(max(||xi||^2 + ||xj||^2 - 2*dot(xi,xj), 0))
// R9: TF32 mma.sync.m16n8k8, 128-thread CTA, 4 warps in 2x2 grid,
// warp tile 64x64 (halves ldmatrix duplication vs R8). Inputs pre-scaled by
// +sqrt2 (A) / -sqrt2 (B) so the MMA produces -2*dot directly; accumulators
// initialized with si+sj so the epilogue is just sqrt(max(acc,0)).

#define NPTS 16384
#define SQRT2P 1.41421356237309515f

__device__ __forceinline__ float sqrt_approx(float v) {
    float r; asm("sqrt.approx.f32 %0, %1;" : "=f"(r) : "f"(v)); return r;
}
__device__ __forceinline__ uint32_t smem_u32(const void* p) {
    return (uint32_t)__cvta_generic_to_shared(p);
}
__device__ __forceinline__ uint32_t tf32_rna(float f) {
    uint32_t u; asm("cvt.rna.tf32.f32 %0, %1;" : "=r"(u) : "f"(f)); return u;
}
__device__ __forceinline__ void ldmatrix_x4(uint32_t* r, uint32_t addr) {
    asm volatile("ldmatrix.sync.aligned.m8n8.x4.shared.b16 {%0,%1,%2,%3}, [%4];"
                 : "=r"(r[0]), "=r"(r[1]), "=r"(r[2]), "=r"(r[3]) : "r"(addr));
}
__device__ __forceinline__ void mma_tf32(float* c, const uint32_t* a,
                                         uint32_t b0, uint32_t b1) {
    asm volatile(
        "mma.sync.aligned.m16n8k8.row.col.f32.tf32.tf32.f32 "
        "{%0,%1,%2,%3}, {%4,%5,%6,%7}, {%8,%9}, {%0,%1,%2,%3};"
        : "+f"(c[0]), "+f"(c[1]), "+f"(c[2]), "+f"(c[3])
        : "r"(a[0]), "r"(a[1]), "r"(a[2]), "r"(a[3]), "r"(b0), "r"(b1));
}

// 16B store into SW128-swizzled [128 rows][128B] tile: chunk c of row r lands
// at r*128 + ((c ^ (r&7))*16).
__device__ __forceinline__ void st16_sw(uint8_t* buf, int row, int chunk, uint4 v) {
    *(uint4*)(buf + row * 128 + (((uint32_t)chunk ^ (row & 7)) << 4)) = v;
}

// Convert one full row (32 floats) scaled by `scale` to tf32, store swizzled;
// return exact fp32 sumsq of the RAW row.
__device__ __forceinline__ float cvt_row(uint8_t* __restrict__ buf, int row,
                                         const float4* __restrict__ src, float scale)
{
    float s = 0.0f;
#pragma unroll
    for (int q = 0; q < 8; q++) {
        float4 v = src[q];
        s = fmaf(v.x, v.x, s); s = fmaf(v.y, v.y, s);
        s = fmaf(v.z, v.z, s); s = fmaf(v.w, v.w, s);
        uint4 w = make_uint4(tf32_rna(scale * v.x), tf32_rna(scale * v.y),
                             tf32_rna(scale * v.z), tf32_rna(scale * v.w));
        st16_sw(buf, row, q, w);
    }
    return s;
}

__global__ void __launch_bounds__(128, 2)
cdist_tf32_kernel(const float* __restrict__ x, float* __restrict__ out)
{
    __shared__ __align__(128) uint8_t Abuf[128 * 128];
    __shared__ __align__(128) uint8_t Bbuf[128 * 128];
    __shared__ float sqa[128];
    __shared__ float sqb[128];

    const int t    = threadIdx.x;
    const int lane = t & 31;
    const int wid  = t >> 5;
    const int a0   = blockIdx.y << 7;
    const int b0   = blockIdx.x << 7;

    // ---- load + tf32-round; thread t handles A row t and B row t ----
    // B rows permuted within each 16-group (STG.128 epilogue permutation):
    //   invperm (global v -> smem slot): ((w&1)<<3)|((w>>1)<<1)|r, w=(v&15)>>1, r=v&1
    {
        const int v = t & 15, w = v >> 1, r = v & 1;
        const int srowB = (t & ~15) | ((w & 1) << 3) | ((w >> 1) << 1) | r;
        const float4* xa = (const float4*)(x + ((size_t)(a0 + t) << 5));
        const float4* xb = (const float4*)(x + ((size_t)(b0 + t) << 5));
        sqa[t] = cvt_row(Abuf, t,     xa,  SQRT2P);
        sqb[t] = cvt_row(Bbuf, srowB, xb, -SQRT2P);
    }
    __syncthreads();

    // ---- warp GEMM: 2x2 warp grid, warp tile 64x64, 4 k8 steps ----
    const int wr = wid >> 1;
    const int wc = wid & 1;
    const uint32_t lx = (uint32_t)(lane & 7);

    // A x4 (per mt, per ks): row wr*64 + mt*16 + (l&7) + 8*((l>>3)&1),
    //                        chunk 2ks + (l>>4)
    const uint32_t aRow  = (uint32_t)(wr * 64) + lx + (((uint32_t)(lane >> 3) & 1) << 3);
    const uint32_t aBase = smem_u32(Abuf) + aRow * 128;
    const uint32_t aCsel = (uint32_t)(lane >> 4);           // 0..1
    // B x4 (per nt-PAIR v, per ks): row wc*64 + v*16 + (l&7) + 8*(l>>4),
    //                               chunk 2ks + ((l>>3)&1)
    const uint32_t bRow  = (uint32_t)(wc * 64) + lx + (((uint32_t)(lane >> 4)) << 3);
    const uint32_t bBase = smem_u32(Bbuf) + bRow * 128;
    const uint32_t bCsel = (uint32_t)((lane >> 3) & 1);     // 0..1

    // ---- init accumulators with si + sj ----
    const int q  = lane & 3;
    const int gr = lane >> 2;
    float acc[4][8][4];
    {
        float4 sj[4];
#pragma unroll
        for (int u = 0; u < 4; u++)
            sj[u] = *(const float4*)&sqb[wc * 64 + u * 16 + q * 4];
#pragma unroll
        for (int mt = 0; mt < 4; mt++) {
            const float si0 = sqa[wr * 64 + mt * 16 + gr];
            const float si1 = sqa[wr * 64 + mt * 16 + gr + 8];
#pragma unroll
            for (int u = 0; u < 4; u++) {
                acc[mt][2 * u][0]     = si0 + sj[u].x;
                acc[mt][2 * u][1]     = si0 + sj[u].y;
                acc[mt][2 * u][2]     = si1 + sj[u].x;
                acc[mt][2 * u][3]     = si1 + sj[u].y;
                acc[mt][2 * u + 1][0] = si0 + sj[u].z;
                acc[mt][2 * u + 1][1] = si0 + sj[u].w;
                acc[mt][2 * u + 1][2] = si1 + sj[u].z;
                acc[mt][2 * u + 1][3] = si1 + sj[u].w;
            }
        }
    }

#pragma unroll
    for (int ks = 0; ks < 4; ks++) {
        const uint32_t aCh = (((uint32_t)(2 * ks) + aCsel) ^ lx) << 4;
        const uint32_t bCh = (((uint32_t)(2 * ks) + bCsel) ^ lx) << 4;
        uint32_t af[4][4], bf[4][4];
#pragma unroll
        for (int mt = 0; mt < 4; mt++)
            ldmatrix_x4(af[mt], aBase + (uint32_t)mt * 2048 + aCh);
#pragma unroll
        for (int v = 0; v < 4; v++)
            ldmatrix_x4(bf[v], bBase + (uint32_t)v * 2048 + bCh);
#pragma unroll
        for (int mt = 0; mt < 4; mt++)
#pragma unroll
            for (int nt = 0; nt < 8; nt++)
                mma_tf32(acc[mt][nt], af[mt],
                         bf[nt >> 1][(nt & 1) * 2], bf[nt >> 1][(nt & 1) * 2 + 1]);
    }

    // ---- epilogue: d = sqrt(max(acc, 0)), STG.128 ----
    const bool diag = (a0 == b0);
#pragma unroll
    for (int mt = 0; mt < 4; mt++) {
        const int r0l = wr * 64 + mt * 16 + gr;
        const int g0 = a0 + r0l, g1 = g0 + 8;
        float* __restrict__ o0 = out + ((size_t)g0 << 14);
        float* __restrict__ o1 = out + ((size_t)g1 << 14);
#pragma unroll
        for (int u = 0; u < 4; u++) {
            const int gc = b0 + wc * 64 + u * 16 + q * 4;
            const float* p0 = acc[mt][2 * u];
            const float* p1 = acc[mt][2 * u + 1];
            float4 w0, w1;
            w0.x = sqrt_approx(fmaxf(p0[0], 0.0f));
            w0.y = sqrt_approx(fmaxf(p0[1], 0.0f));
            w0.z = sqrt_approx(fmaxf(p1[0], 0.0f));
            w0.w = sqrt_approx(fmaxf(p1[1], 0.0f));
            w1.x = sqrt_approx(fmaxf(p0[2], 0.0f));
            w1.y = sqrt_approx(fmaxf(p0[3], 0.0f));
            w1.z = sqrt_approx(fmaxf(p1[2], 0.0f));
            w1.w = sqrt_approx(fmaxf(p1[3], 0.0f));
            if (diag) {
                const int d0 = g0 - gc;
                if (d0 >= 0 && d0 < 4) ((float*)&w0)[d0] = 0.0f;
                const int d1 = g1 - gc;
                if (d1 >= 0 && d1 < 4) ((float*)&w1)[d1] = 0.0f;
            }
            *(float4*)(o0 + gc) = w0;
            *(float4*)(o1 + gc) = w1;
        }
    }
}

extern "C" void kernel_launch(void* const* d_in, const int* in_sizes, int n_in,
                              void* d_out, int out_size)
{
    (void)in_sizes; (void)n_in; (void)out_size;
    const float* x = (const float*)d_in[0];
    float* out = (float*)d_out;
    dim3 grid(NPTS / 128, NPTS / 128);
    cdist_tf32_kernel<<<grid, 128>>>(x, out);
}

// round 10
// speedup vs baseline: 1.1335x; 1.1335x over previous
#include <cuda_runtime.h>
#include <stdint.h>

// cdist: out[i,j] = sqrt(max(||xi||^2 + ||xj||^2 - 2*dot(xi,xj), 0))
// R10: R8 geometry (proven fastest: 256 thr, 2x4 warps, 64x32 warp tiles,
// TF32 m16n8k8) + R9's numerics trick: A stored as tf32(+sqrt2*x), B as
// tf32(-sqrt2*x), accumulators initialized to si+sj, so the MMA emits d^2
// directly and the epilogue is sqrt(max(acc,0)) with streaming stores.

#define NPTS 16384
#define SQRT2P 1.41421356237309515f

__device__ __forceinline__ float sqrt_approx(float v) {
    float r; asm("sqrt.approx.f32 %0, %1;" : "=f"(r) : "f"(v)); return r;
}
__device__ __forceinline__ uint32_t smem_u32(const void* p) {
    return (uint32_t)__cvta_generic_to_shared(p);
}
__device__ __forceinline__ uint32_t tf32_rna(float f) {
    uint32_t u; asm("cvt.rna.tf32.f32 %0, %1;" : "=r"(u) : "f"(f)); return u;
}
__device__ __forceinline__ void ldmatrix_x4(uint32_t* r, uint32_t addr) {
    asm volatile("ldmatrix.sync.aligned.m8n8.x4.shared.b16 {%0,%1,%2,%3}, [%4];"
                 : "=r"(r[0]), "=r"(r[1]), "=r"(r[2]), "=r"(r[3]) : "r"(addr));
}
__device__ __forceinline__ void mma_tf32(float* c, const uint32_t* a,
                                         uint32_t b0, uint32_t b1) {
    asm volatile(
        "mma.sync.aligned.m16n8k8.row.col.f32.tf32.tf32.f32 "
        "{%0,%1,%2,%3}, {%4,%5,%6,%7}, {%8,%9}, {%0,%1,%2,%3};"
        : "+f"(c[0]), "+f"(c[1]), "+f"(c[2]), "+f"(c[3])
        : "r"(a[0]), "r"(a[1]), "r"(a[2]), "r"(a[3]), "r"(b0), "r"(b1));
}
__device__ __forceinline__ void stg_cs(float* p, float4 v) {
    asm volatile("st.global.cs.v4.f32 [%0], {%1,%2,%3,%4};"
                 :: "l"(p), "f"(v.x), "f"(v.y), "f"(v.z), "f"(v.w) : "memory");
}

// 16B store into SW128-swizzled [128 rows][128B] tile: chunk c of row r lands
// at r*128 + ((c ^ (r&7))*16).
__device__ __forceinline__ void st16_sw(uint8_t* buf, int row, int chunk, uint4 v) {
    *(uint4*)(buf + row * 128 + (((uint32_t)chunk ^ (row & 7)) << 4)) = v;
}

// Convert half a row (16 floats), scaled, to tf32; store swizzled; return raw sumsq.
__device__ __forceinline__ float cvt_store(uint8_t* __restrict__ buf, int row,
                                           int half, const float4* __restrict__ src,
                                           float scale)
{
    float s = 0.0f;
#pragma unroll
    for (int q = 0; q < 4; q++) {
        float4 v = src[q];
        s = fmaf(v.x, v.x, s); s = fmaf(v.y, v.y, s);
        s = fmaf(v.z, v.z, s); s = fmaf(v.w, v.w, s);
        uint4 w = make_uint4(tf32_rna(scale * v.x), tf32_rna(scale * v.y),
                             tf32_rna(scale * v.z), tf32_rna(scale * v.w));
        st16_sw(buf, row, half * 4 + q, w);
    }
    return s;
}

__global__ void __launch_bounds__(256, 2)
cdist_tf32_kernel(const float* __restrict__ x, float* __restrict__ out)
{
    __shared__ __align__(128) uint8_t Abuf[128 * 128];
    __shared__ __align__(128) uint8_t Bbuf[128 * 128];
    __shared__ float sqa[128];
    __shared__ float sqb[128];

    const int t    = threadIdx.x;
    const int lane = t & 31;
    const int wid  = t >> 5;
    const int a0   = blockIdx.y << 7;
    const int b0   = blockIdx.x << 7;

    // ---- load + tf32-round (thread t: row t/2, half t&1) ----
    // B rows permuted within each 16-group (STG.128 epilogue permutation):
    //   invperm (global v -> smem slot): ((w&1)<<3)|((w>>1)<<1)|r, w=(v&15)>>1, r=v&1
    {
        const int row  = t >> 1;
        const int half = t & 1;
        const int v = row & 15, w = v >> 1, r = v & 1;
        const int srowB = (row & ~15) | ((w & 1) << 3) | ((w >> 1) << 1) | r;
        const float4* xa = (const float4*)(x + ((size_t)(a0 + row) << 5)) + half * 4;
        const float4* xb = (const float4*)(x + ((size_t)(b0 + row) << 5)) + half * 4;
        float sa = cvt_store(Abuf, row,   half, xa,  SQRT2P);
        float sb = cvt_store(Bbuf, srowB, half, xb, -SQRT2P);
        sa += __shfl_xor_sync(0xFFFFFFFFu, sa, 1);
        sb += __shfl_xor_sync(0xFFFFFFFFu, sb, 1);
        if (!half) { sqa[row] = sa; sqb[row] = sb; }
    }
    __syncthreads();

    // ---- warp GEMM: warp tile 64x32, 4 k-steps of k8 ----
    const int wr = wid >> 2;
    const int wc = wid & 3;
    const uint32_t lx = (uint32_t)(lane & 7);

    const uint32_t aRow  = (uint32_t)(wr * 64) + lx + (((uint32_t)(lane >> 3) & 1) << 3);
    const uint32_t aBase = smem_u32(Abuf) + aRow * 128;
    const uint32_t aCsel = (uint32_t)(lane >> 4);          // 0..1
    const uint32_t bRow  = (uint32_t)(wc * 32) + lx;
    const uint32_t bBase = smem_u32(Bbuf) + bRow * 128;
    const uint32_t bCsel = (uint32_t)(lane >> 3);          // 0..3

    // ---- init accumulators with si + sj (exact fp32) ----
    const int q  = lane & 3;
    const int gr = lane >> 2;
    float acc[4][4][4];
    {
        float4 sj[2];
        sj[0] = *(const float4*)&sqb[wc * 32 + q * 4];
        sj[1] = *(const float4*)&sqb[wc * 32 + 16 + q * 4];
#pragma unroll
        for (int mt = 0; mt < 4; mt++) {
            const float si0 = sqa[wr * 64 + mt * 16 + gr];
            const float si1 = sqa[wr * 64 + mt * 16 + gr + 8];
#pragma unroll
            for (int u = 0; u < 2; u++) {
                acc[mt][2 * u][0]     = si0 + sj[u].x;
                acc[mt][2 * u][1]     = si0 + sj[u].y;
                acc[mt][2 * u][2]     = si1 + sj[u].x;
                acc[mt][2 * u][3]     = si1 + sj[u].y;
                acc[mt][2 * u + 1][0] = si0 + sj[u].z;
                acc[mt][2 * u + 1][1] = si0 + sj[u].w;
                acc[mt][2 * u + 1][2] = si1 + sj[u].z;
                acc[mt][2 * u + 1][3] = si1 + sj[u].w;
            }
        }
    }

#pragma unroll
    for (int kp = 0; kp < 2; kp++) {
        // B frags for 2 k-steps: regs {b0_ks0, b1_ks0, b0_ks1, b1_ks1}
        uint32_t bp[4][4];
        const uint32_t bCh = (((uint32_t)(4 * kp) + bCsel) ^ lx) << 4;
#pragma unroll
        for (int nt = 0; nt < 4; nt++)
            ldmatrix_x4(bp[nt], bBase + (uint32_t)nt * 1024 + bCh);

#pragma unroll
        for (int k2 = 0; k2 < 2; k2++) {
            const int ks = 2 * kp + k2;
            const uint32_t aCh = (((uint32_t)(2 * ks) + aCsel) ^ lx) << 4;
            uint32_t af[4][4];
#pragma unroll
            for (int mt = 0; mt < 4; mt++)
                ldmatrix_x4(af[mt], aBase + (uint32_t)mt * 2048 + aCh);
#pragma unroll
            for (int mt = 0; mt < 4; mt++)
#pragma unroll
                for (int nt = 0; nt < 4; nt++)
                    mma_tf32(acc[mt][nt], af[mt],
                             bp[nt][2 * k2], bp[nt][2 * k2 + 1]);
        }
    }

    // ---- epilogue: d = sqrt(max(acc, 0)), streaming STG.128 ----
    const bool diag = (a0 == b0);
#pragma unroll
    for (int mt = 0; mt < 4; mt++) {
        const int r0l = wr * 64 + mt * 16 + gr;
        const int g0 = a0 + r0l, g1 = g0 + 8;
        float* __restrict__ o0 = out + ((size_t)g0 << 14);
        float* __restrict__ o1 = out + ((size_t)g1 << 14);
#pragma unroll
        for (int u = 0; u < 2; u++) {
            const int gc = b0 + wc * 32 + u * 16 + q * 4;
            const float* p0 = acc[mt][2 * u];
            const float* p1 = acc[mt][2 * u + 1];
            float4 w0, w1;
            w0.x = sqrt_approx(fmaxf(p0[0], 0.0f));
            w0.y = sqrt_approx(fmaxf(p0[1], 0.0f));
            w0.z = sqrt_approx(fmaxf(p1[0], 0.0f));
            w0.w = sqrt_approx(fmaxf(p1[1], 0.0f));
            w1.x = sqrt_approx(fmaxf(p0[2], 0.0f));
            w1.y = sqrt_approx(fmaxf(p0[3], 0.0f));
            w1.z = sqrt_approx(fmaxf(p1[2], 0.0f));
            w1.w = sqrt_approx(fmaxf(p1[3], 0.0f));
            if (diag) {
                const int d0 = g0 - gc;
                if (d0 >= 0 && d0 < 4) ((float*)&w0)[d0] = 0.0f;
                const int d1 = g1 - gc;
                if (d1 >= 0 && d1 < 4) ((float*)&w1)[d1] = 0.0f;
            }
            stg_cs(o0 + gc, w0);
            stg_cs(o1 + gc, w1);
        }
    }
}

extern "C" void kernel_launch(void* const* d_in, const int* in_sizes, int n_in,
                              void* d_out, int out_size)
{
    (void)in_sizes; (void)n_in; (void)out_size;
    const float* x = (const float*)d_in[0];
    float* out = (float*)d_out;
    dim3 grid(NPTS / 128, NPTS / 128);
    cdist_tf32_kernel<<<grid, 256>>>(x, out);
}